// round 3
// baseline (speedup 1.0000x reference)
#include <cuda_runtime.h>
#include <math.h>

#define S_LEN 2048
#define H_DIM 4096
#define NQH 32
#define NKVH 8
#define HDIM 128

// Scratch (device globals; no allocation allowed)
__device__ float g_Q[S_LEN * H_DIM];          // 2048 x (32*128)
__device__ float g_K[S_LEN * NKVH * HDIM];    // 2048 x 1024
__device__ float g_V[S_LEN * NKVH * HDIM];
__device__ float g_Ctx[S_LEN * H_DIM];

// ---------------------------------------------------------------------------
// 128x128x8 tiled SGEMM, row-major A[M,K] * B[K,N] -> C[M,N]
// 256 threads, 8x8 microtile per thread, prefetch next K-tile into registers.
// Assumes M%128==0, N%128==0, K%8==0 (true for all shapes here).
// ---------------------------------------------------------------------------
__global__ __launch_bounds__(256) void gemm128(
    const float* __restrict__ A, const float* __restrict__ B,
    float* __restrict__ C, int N, int K) {
  __shared__ float As[8][128];
  __shared__ float Bs[8][128];
  const int tid = threadIdx.x;
  const int tx = tid & 15, ty = tid >> 4;
  const int bm = blockIdx.y * 128, bn = blockIdx.x * 128;

  const int arow = tid >> 1;           // 0..127
  const int acol = (tid & 1) << 2;     // 0 or 4
  const int brow = tid >> 5;           // 0..7
  const int bcol = (tid & 31) << 2;    // 0..124

  const float* Ap = A + (size_t)(bm + arow) * K + acol;
  const float* Bp = B + (size_t)brow * N + bn + bcol;

  float4 aReg = *(const float4*)Ap;
  float4 bReg = *(const float4*)Bp;

  float acc[8][8];
#pragma unroll
  for (int i = 0; i < 8; i++)
#pragma unroll
    for (int j = 0; j < 8; j++) acc[i][j] = 0.f;

  const int ntiles = K >> 3;
  for (int t = 0; t < ntiles; ++t) {
    As[acol + 0][arow] = aReg.x;
    As[acol + 1][arow] = aReg.y;
    As[acol + 2][arow] = aReg.z;
    As[acol + 3][arow] = aReg.w;
    *(float4*)&Bs[brow][bcol] = bReg;
    __syncthreads();
    if (t + 1 < ntiles) {
      aReg = *(const float4*)(Ap + (size_t)(t + 1) * 8);
      bReg = *(const float4*)(Bp + (size_t)(t + 1) * 8 * N);
    }
#pragma unroll
    for (int kk = 0; kk < 8; ++kk) {
      float4 a0 = *(const float4*)&As[kk][ty * 8];
      float4 a1 = *(const float4*)&As[kk][ty * 8 + 4];
      float4 b0 = *(const float4*)&Bs[kk][tx * 8];
      float4 b1 = *(const float4*)&Bs[kk][tx * 8 + 4];
      float a[8] = {a0.x, a0.y, a0.z, a0.w, a1.x, a1.y, a1.z, a1.w};
      float b[8] = {b0.x, b0.y, b0.z, b0.w, b1.x, b1.y, b1.z, b1.w};
#pragma unroll
      for (int i = 0; i < 8; i++)
#pragma unroll
        for (int j = 0; j < 8; j++) acc[i][j] = fmaf(a[i], b[j], acc[i][j]);
    }
    __syncthreads();
  }
#pragma unroll
  for (int i = 0; i < 8; i++) {
    float* Cp = C + (size_t)(bm + ty * 8 + i) * N + bn + tx * 8;
    *(float4*)Cp = make_float4(acc[i][0], acc[i][1], acc[i][2], acc[i][3]);
    *(float4*)(Cp + 4) = make_float4(acc[i][4], acc[i][5], acc[i][6], acc[i][7]);
  }
}

// ---------------------------------------------------------------------------
// RoPE in place on Q [S, 32, 128] and K [S, 8, 128].
// For d<64: out_d = x_d*cos_d - x_{d+64}*sin_d
//           out_{d+64} = x_{d+64}*cos_{d+64} + x_d*sin_{d+64}
// ---------------------------------------------------------------------------
__global__ void rope_kernel(float* __restrict__ Q, float* __restrict__ K,
                            const float* __restrict__ cosp,
                            const float* __restrict__ sinp) {
  int idx = blockIdx.x * blockDim.x + threadIdx.x;
  const int total_q = S_LEN * NQH * 64;
  const int total_k = S_LEN * NKVH * 64;
  if (idx < total_q) {
    int d = idx & 63;
    int h = (idx >> 6) & 31;
    int s = idx >> 11;  // /(64*32)
    float c1 = cosp[s * 128 + d], s1 = sinp[s * 128 + d];
    float c2 = cosp[s * 128 + d + 64], s2 = sinp[s * 128 + d + 64];
    float* base = Q + (size_t)s * H_DIM + h * 128;
    float x1 = base[d], x2 = base[d + 64];
    base[d] = x1 * c1 - x2 * s1;
    base[d + 64] = x2 * c2 + x1 * s2;
  } else if (idx < total_q + total_k) {
    idx -= total_q;
    int d = idx & 63;
    int h = (idx >> 6) & 7;
    int s = idx >> 9;  // /(64*8)
    float c1 = cosp[s * 128 + d], s1 = sinp[s * 128 + d];
    float c2 = cosp[s * 128 + d + 64], s2 = sinp[s * 128 + d + 64];
    float* base = K + (size_t)s * (NKVH * HDIM) + h * 128;
    float x1 = base[d], x2 = base[d + 64];
    base[d] = x1 * c1 - x2 * s1;
    base[d + 64] = x2 * c2 + x1 * s2;
  }
}

// ---------------------------------------------------------------------------
// Causal flash attention, fp32, GQA (4 q-heads per kv-head).
// Grid: (qblock 0..31, head 0..31). 256 threads.
// BLOCK_M = BLOCK_N = 64, HD = 128.
// SMEM: Qts[128][64] + Kts[128][64] + Vs[64][128] + Ps[64][64] = 112 KB dyn.
// ---------------------------------------------------------------------------
__global__ __launch_bounds__(256) void flash_attn(
    const float* __restrict__ Q, const float* __restrict__ K,
    const float* __restrict__ V, float* __restrict__ Ctx) {
  extern __shared__ float sm[];
  float* Qts = sm;             // [128][64] (d-major, transposed)
  float* Kts = sm + 8192;      // [128][64]
  float* Vs  = sm + 16384;     // [64][128]
  float* Ps  = sm + 24576;     // [64][64]

  const int tid = threadIdx.x;
  const int tx = tid & 15, ty = tid >> 4;
  const int qb = blockIdx.x, hq = blockIdx.y, hkv = hq >> 2;
  const float scale = 0.08838834764831845f;  // 1/sqrt(128)

  // Load Q block (64 x 128), store transposed
#pragma unroll
  for (int t = 0; t < 8; ++t) {
    int idx = tid + t * 256;
    int r = idx >> 5;
    int d = (idx & 31) << 2;
    float4 q = *(const float4*)&Q[(size_t)(qb * 64 + r) * H_DIM + hq * 128 + d];
    Qts[(d + 0) * 64 + r] = q.x;
    Qts[(d + 1) * 64 + r] = q.y;
    Qts[(d + 2) * 64 + r] = q.z;
    Qts[(d + 3) * 64 + r] = q.w;
  }

  float o[4][8];
  float m_i[4], l_i[4];
#pragma unroll
  for (int i = 0; i < 4; i++) {
    m_i[i] = -1e30f;
    l_i[i] = 0.f;
#pragma unroll
    for (int j = 0; j < 8; j++) o[i][j] = 0.f;
  }

  for (int kb = 0; kb <= qb; ++kb) {
    // Load K (transposed) and V blocks
#pragma unroll
    for (int t = 0; t < 8; ++t) {
      int idx = tid + t * 256;
      int r = idx >> 5;
      int d = (idx & 31) << 2;
      size_t g = (size_t)(kb * 64 + r) * (NKVH * HDIM) + hkv * 128 + d;
      float4 k = *(const float4*)&K[g];
      Kts[(d + 0) * 64 + r] = k.x;
      Kts[(d + 1) * 64 + r] = k.y;
      Kts[(d + 2) * 64 + r] = k.z;
      Kts[(d + 3) * 64 + r] = k.w;
      float4 v = *(const float4*)&V[g];
      *(float4*)&Vs[r * 128 + d] = v;
    }
    __syncthreads();

    // S = Q @ K^T  (each thread: 4 rows x 4 cols)
    float s[4][4];
#pragma unroll
    for (int i = 0; i < 4; i++)
#pragma unroll
      for (int j = 0; j < 4; j++) s[i][j] = 0.f;

#pragma unroll 4
    for (int d = 0; d < 128; ++d) {
      float4 a4 = *(const float4*)&Qts[d * 64 + ty * 4];
      float4 b4 = *(const float4*)&Kts[d * 64 + tx * 4];
      float a[4] = {a4.x, a4.y, a4.z, a4.w};
      float b[4] = {b4.x, b4.y, b4.z, b4.w};
#pragma unroll
      for (int i = 0; i < 4; i++)
#pragma unroll
        for (int j = 0; j < 4; j++) s[i][j] = fmaf(a[i], b[j], s[i][j]);
    }

#pragma unroll
    for (int i = 0; i < 4; i++)
#pragma unroll
      for (int j = 0; j < 4; j++) s[i][j] *= scale;

    if (kb == qb) {
#pragma unroll
      for (int i = 0; i < 4; i++)
#pragma unroll
        for (int j = 0; j < 4; j++)
          if (tx * 4 + j > ty * 4 + i) s[i][j] = -1e30f;
    }

    // Online softmax (row stats shared across 16 tx lanes via shfl)
#pragma unroll
    for (int i = 0; i < 4; i++) {
      float mx = fmaxf(fmaxf(s[i][0], s[i][1]), fmaxf(s[i][2], s[i][3]));
      mx = fmaxf(mx, __shfl_xor_sync(0xffffffffu, mx, 1));
      mx = fmaxf(mx, __shfl_xor_sync(0xffffffffu, mx, 2));
      mx = fmaxf(mx, __shfl_xor_sync(0xffffffffu, mx, 4));
      mx = fmaxf(mx, __shfl_xor_sync(0xffffffffu, mx, 8));
      float mnew = fmaxf(m_i[i], mx);
      float al = __expf(m_i[i] - mnew);
      float sum = 0.f;
#pragma unroll
      for (int j = 0; j < 4; j++) {
        s[i][j] = __expf(s[i][j] - mnew);
        sum += s[i][j];
      }
      sum += __shfl_xor_sync(0xffffffffu, sum, 1);
      sum += __shfl_xor_sync(0xffffffffu, sum, 2);
      sum += __shfl_xor_sync(0xffffffffu, sum, 4);
      sum += __shfl_xor_sync(0xffffffffu, sum, 8);
      l_i[i] = l_i[i] * al + sum;
      m_i[i] = mnew;
#pragma unroll
      for (int j = 0; j < 8; j++) o[i][j] *= al;
      *(float4*)&Ps[(ty * 4 + i) * 64 + tx * 4] =
          make_float4(s[i][0], s[i][1], s[i][2], s[i][3]);
    }
    __syncthreads();

    // O += P @ V  (each thread: 4 rows x 8 dims at tx*8)
#pragma unroll 2
    for (int kk = 0; kk < 64; ++kk) {
      float p0 = Ps[(ty * 4 + 0) * 64 + kk];
      float p1 = Ps[(ty * 4 + 1) * 64 + kk];
      float p2 = Ps[(ty * 4 + 2) * 64 + kk];
      float p3 = Ps[(ty * 4 + 3) * 64 + kk];
      float4 v0 = *(const float4*)&Vs[kk * 128 + tx * 8];
      float4 v1 = *(const float4*)&Vs[kk * 128 + tx * 8 + 4];
      float vv[8] = {v0.x, v0.y, v0.z, v0.w, v1.x, v1.y, v1.z, v1.w};
#pragma unroll
      for (int j = 0; j < 8; j++) {
        o[0][j] = fmaf(p0, vv[j], o[0][j]);
        o[1][j] = fmaf(p1, vv[j], o[1][j]);
        o[2][j] = fmaf(p2, vv[j], o[2][j]);
        o[3][j] = fmaf(p3, vv[j], o[3][j]);
      }
    }
    __syncthreads();
  }

  // Epilogue: normalize and write context
#pragma unroll
  for (int i = 0; i < 4; i++) {
    float inv = 1.0f / l_i[i];
    float* Cp = Ctx + (size_t)(qb * 64 + ty * 4 + i) * H_DIM + hq * 128 + tx * 8;
    *(float4*)Cp =
        make_float4(o[i][0] * inv, o[i][1] * inv, o[i][2] * inv, o[i][3] * inv);
    *(float4*)(Cp + 4) =
        make_float4(o[i][4] * inv, o[i][5] * inv, o[i][6] * inv, o[i][7] * inv);
  }
}

// ---------------------------------------------------------------------------
// Launch
// ---------------------------------------------------------------------------
extern "C" void kernel_launch(void* const* d_in, const int* in_sizes, int n_in,
                              void* d_out, int out_size) {
  const float* X    = (const float*)d_in[0];
  const float* cosp = (const float*)d_in[1];
  const float* sinp = (const float*)d_in[2];
  const float* wq   = (const float*)d_in[3];
  const float* wk   = (const float*)d_in[4];
  const float* wv   = (const float*)d_in[5];
  const float* wo   = (const float*)d_in[6];
  float* out = (float*)d_out;

  float *Q, *K, *V, *Ctx;
  cudaGetSymbolAddress((void**)&Q, g_Q);
  cudaGetSymbolAddress((void**)&K, g_K);
  cudaGetSymbolAddress((void**)&V, g_V);
  cudaGetSymbolAddress((void**)&Ctx, g_Ctx);

  const int FLASH_SMEM = 114688;  // 112 KB
  cudaFuncSetAttribute(flash_attn, cudaFuncAttributeMaxDynamicSharedMemorySize,
                       FLASH_SMEM);

  dim3 blk(256);
  // QKV projections
  gemm128<<<dim3(32, 16), blk>>>(X, wq, Q, 4096, 4096);
  gemm128<<<dim3(8, 16), blk>>>(X, wk, K, 1024, 4096);
  gemm128<<<dim3(8, 16), blk>>>(X, wv, V, 1024, 4096);
  // RoPE
  int rope_total = S_LEN * (NQH + NKVH) * 64;
  rope_kernel<<<(rope_total + 255) / 256, 256>>>(Q, K, cosp, sinp);
  // Attention
  flash_attn<<<dim3(32, 32), blk, FLASH_SMEM>>>(Q, K, V, Ctx);
  // Output projection
  gemm128<<<dim3(32, 16), blk>>>(Ctx, wo, out, 4096, 4096);
}

// round 6
// speedup vs baseline: 1.6235x; 1.6235x over previous
#include <cuda_runtime.h>
#include <cuda_bf16.h>
#include <math.h>
#include <stdint.h>

#define S_LEN 2048
#define H_DIM 4096
#define NQH 32
#define NKVH 8
#define HDIM 128
#define KDIM 4096

// ---------------------------------------------------------------------------
// Scratch (device globals; no allocation allowed)
// ---------------------------------------------------------------------------
__device__ float g_Q[S_LEN * H_DIM];
__device__ float g_K[S_LEN * NKVH * HDIM];
__device__ float g_V[S_LEN * NKVH * HDIM];
__device__ float g_Ctx[S_LEN * H_DIM];

// bf16 split operands
__device__ __nv_bfloat16 g_Ahi[S_LEN * KDIM];   // activations hi
__device__ __nv_bfloat16 g_Alo[S_LEN * KDIM];   // activations lo
__device__ __nv_bfloat16 g_Bhi[KDIM * KDIM];    // weights (transposed, [N,K]) hi
__device__ __nv_bfloat16 g_Blo[KDIM * KDIM];    // weights lo

// ---------------------------------------------------------------------------
// Helpers
// ---------------------------------------------------------------------------
__device__ __forceinline__ uint32_t smem_u32(const void* p) {
  uint32_t a;
  asm("{ .reg .u64 t; cvta.to.shared.u64 t, %1; cvt.u32.u64 %0, t; }"
      : "=r"(a) : "l"(p));
  return a;
}

__device__ __forceinline__ void cp16(uint32_t dst, const void* src) {
  asm volatile("cp.async.cg.shared.global [%0], [%1], 16;" ::"r"(dst), "l"(src));
}

#define LDSM4(R, ADDR)                                                       \
  asm volatile("ldmatrix.sync.aligned.m8n8.x4.shared.b16 {%0,%1,%2,%3}, [%4];" \
               : "=r"((R)[0]), "=r"((R)[1]), "=r"((R)[2]), "=r"((R)[3])      \
               : "r"(ADDR))

#define MMA16816(D, A, B)                                                    \
  asm volatile(                                                              \
      "mma.sync.aligned.m16n8k16.row.col.f32.bf16.bf16.f32 "                \
      "{%0,%1,%2,%3}, {%4,%5,%6,%7}, {%8,%9}, {%0,%1,%2,%3};"               \
      : "+f"((D)[0]), "+f"((D)[1]), "+f"((D)[2]), "+f"((D)[3])              \
      : "r"((A)[0]), "r"((A)[1]), "r"((A)[2]), "r"((A)[3]), "r"((B)[0]),    \
        "r"((B)[1]))

// ---------------------------------------------------------------------------
// Split-convert fp32 -> bf16 hi/lo (row-major, same layout)
// ---------------------------------------------------------------------------
__global__ void split_convert(const float* __restrict__ X,
                              __nv_bfloat16* __restrict__ Hi,
                              __nv_bfloat16* __restrict__ Lo, int n) {
  int i = (blockIdx.x * 256 + threadIdx.x) * 4;
  if (i >= n) return;
  float4 x = *(const float4*)(X + i);
  float v[4] = {x.x, x.y, x.z, x.w};
  __nv_bfloat16 h[4], l[4];
#pragma unroll
  for (int j = 0; j < 4; j++) {
    h[j] = __float2bfloat16_rn(v[j]);
    l[j] = __float2bfloat16_rn(v[j] - __bfloat162float(h[j]));
  }
  __nv_bfloat162 h01, h23, l01, l23;
  h01.x = h[0]; h01.y = h[1]; h23.x = h[2]; h23.y = h[3];
  l01.x = l[0]; l01.y = l[1]; l23.x = l[2]; l23.y = l[3];
  *(__nv_bfloat162*)(Hi + i) = h01;
  *(__nv_bfloat162*)(Hi + i + 2) = h23;
  *(__nv_bfloat162*)(Lo + i) = l01;
  *(__nv_bfloat162*)(Lo + i + 2) = l23;
}

// ---------------------------------------------------------------------------
// Transpose-convert W[K,N] fp32 -> [N,K] bf16 hi/lo
// ---------------------------------------------------------------------------
__global__ void transpose_split(const float* __restrict__ W,
                                __nv_bfloat16* __restrict__ Hi,
                                __nv_bfloat16* __restrict__ Lo, int K, int N) {
  __shared__ float tile[32][33];
  int tx = threadIdx.x, ty = threadIdx.y;
  int k0 = blockIdx.y * 32, n0 = blockIdx.x * 32;
#pragma unroll
  for (int i = 0; i < 4; i++)
    tile[ty + i * 8][tx] = W[(size_t)(k0 + ty + i * 8) * N + n0 + tx];
  __syncthreads();
#pragma unroll
  for (int i = 0; i < 4; i++) {
    float v = tile[tx][ty + i * 8];
    __nv_bfloat16 h = __float2bfloat16_rn(v);
    __nv_bfloat16 l = __float2bfloat16_rn(v - __bfloat162float(h));
    size_t o = (size_t)(n0 + ty + i * 8) * K + k0 + tx;
    Hi[o] = h;
    Lo[o] = l;
  }
}

// ---------------------------------------------------------------------------
// HMMA bf16 split-precision GEMM: C[M,N] = A[M,K] * B^T  (B stored [N,K])
// CTA tile 128x128, BK=32, 8 warps (2x4), warp tile 64x32.
// 3 terms: AhBh + AhBl + AlBh, fp32 accum. 3-stage cp.async pipeline.
// SMEM per stage: 4 matrices x 128 rows x 40 elems (pad 8) x 2B = 40960 B.
// ---------------------------------------------------------------------------
#define NCH (KDIM / 32)
#define MAT_BYTES 10240       // 128 * 40 * 2
#define STAGE_BYTES 40960
#define GEMM_SMEM (3 * STAGE_BYTES)  // 122880

__global__ __launch_bounds__(256, 1) void gemm_mma(
    const __nv_bfloat16* __restrict__ Ahi, const __nv_bfloat16* __restrict__ Alo,
    const __nv_bfloat16* __restrict__ Bhi, const __nv_bfloat16* __restrict__ Blo,
    float* __restrict__ C, int N) {
  extern __shared__ char smc[];
  const int tid = threadIdx.x;
  const int lane = tid & 31, wid = tid >> 5;
  const int wm = wid & 1, wn = wid >> 1;
  const int bm = blockIdx.y * 128, bn = blockIdx.x * 128;
  const size_t Kb = (size_t)KDIM * 2;

  uint32_t sbase = smem_u32(smc);

  const char* gp0 = (const char*)Ahi + (size_t)bm * Kb;
  const char* gp1 = (const char*)Alo + (size_t)bm * Kb;
  const char* gp2 = (const char*)Bhi + (size_t)bn * Kb;
  const char* gp3 = (const char*)Blo + (size_t)bn * Kb;

  // per-thread cp.async mapping: rows r, r+64; 16B col chunk cb
  const int r = tid >> 2;
  const int cb = (tid & 3) * 16;

  auto load_stage = [&](int stage, int k0) {
    uint32_t sb = sbase + stage * STAGE_BYTES;
    size_t gk = (size_t)k0 * 2;
    const char* gp[4] = {gp0, gp1, gp2, gp3};
#pragma unroll
    for (int m = 0; m < 4; m++) {
      uint32_t sd = sb + m * MAT_BYTES;
#pragma unroll
      for (int j = 0; j < 2; j++) {
        int rr = r + j * 64;
        cp16(sd + rr * 80 + cb, gp[m] + (size_t)rr * Kb + gk + cb);
      }
    }
    asm volatile("cp.async.commit_group;" ::: "memory");
  };

  float acc[4][4][4];
#pragma unroll
  for (int a = 0; a < 4; a++)
#pragma unroll
    for (int b = 0; b < 4; b++)
#pragma unroll
      for (int c = 0; c < 4; c++) acc[a][b][c] = 0.f;

  // ldmatrix address components
  const int arow = wm * 64 + (lane & 15);
  const int aoff = (lane >> 4) * 8;
  const int brow = wn * 32 + (lane >> 4) * 8 + (lane & 7);
  const int boff = ((lane >> 3) & 1) * 8;

  load_stage(0, 0);
  load_stage(1, 32);

  for (int i = 0; i < NCH; ++i) {
    if (i + 2 < NCH)
      asm volatile("cp.async.wait_group 1;" ::: "memory");
    else
      asm volatile("cp.async.wait_group 0;" ::: "memory");
    __syncthreads();
    if (i + 2 < NCH) load_stage((i + 2) % 3, (i + 2) * 32);

    uint32_t sb = sbase + (i % 3) * STAGE_BYTES;
    uint32_t sAh = sb;                      // Alo = +MAT_BYTES
    uint32_t sBh = sb + 2 * MAT_BYTES;      // Blo = +MAT_BYTES

#pragma unroll
    for (int ks = 0; ks < 32; ks += 16) {
      uint32_t Ah[4][4], Al[4][4], Bh[4][2], Bl[4][2];
#pragma unroll
      for (int mi = 0; mi < 4; mi++) {
        uint32_t ad = sAh + ((arow + mi * 16) * 40 + ks + aoff) * 2;
        LDSM4(Ah[mi], ad);
        LDSM4(Al[mi], ad + MAT_BYTES);
      }
#pragma unroll
      for (int ni = 0; ni < 2; ni++) {
        uint32_t bd = sBh + ((brow + ni * 16) * 40 + ks + boff) * 2;
        uint32_t t[4];
        LDSM4(t, bd);
        Bh[ni * 2][0] = t[0]; Bh[ni * 2][1] = t[1];
        Bh[ni * 2 + 1][0] = t[2]; Bh[ni * 2 + 1][1] = t[3];
        LDSM4(t, bd + MAT_BYTES);
        Bl[ni * 2][0] = t[0]; Bl[ni * 2][1] = t[1];
        Bl[ni * 2 + 1][0] = t[2]; Bl[ni * 2 + 1][1] = t[3];
      }
#pragma unroll
      for (int mi = 0; mi < 4; mi++)
#pragma unroll
        for (int nj = 0; nj < 4; nj++) {
          MMA16816(acc[mi][nj], Ah[mi], Bh[nj]);
          MMA16816(acc[mi][nj], Ah[mi], Bl[nj]);
          MMA16816(acc[mi][nj], Al[mi], Bh[nj]);
        }
    }
  }

  // Epilogue
  const int tg = lane >> 2, tc = (lane & 3) * 2;
#pragma unroll
  for (int mi = 0; mi < 4; mi++) {
    int row = bm + wm * 64 + mi * 16 + tg;
#pragma unroll
    for (int nj = 0; nj < 4; nj++) {
      int col = bn + wn * 32 + nj * 8 + tc;
      float* p = C + (size_t)row * N + col;
      p[0] = acc[mi][nj][0];
      p[1] = acc[mi][nj][1];
      float* p2 = p + 8 * (size_t)N;
      p2[0] = acc[mi][nj][2];
      p2[1] = acc[mi][nj][3];
    }
  }
}

// ---------------------------------------------------------------------------
// RoPE in place on Q [S, 32, 128] and K [S, 8, 128].
// ---------------------------------------------------------------------------
__global__ void rope_kernel(float* __restrict__ Q, float* __restrict__ K,
                            const float* __restrict__ cosp,
                            const float* __restrict__ sinp) {
  int idx = blockIdx.x * blockDim.x + threadIdx.x;
  const int total_q = S_LEN * NQH * 64;
  const int total_k = S_LEN * NKVH * 64;
  if (idx < total_q) {
    int d = idx & 63;
    int h = (idx >> 6) & 31;
    int s = idx >> 11;
    float c1 = cosp[s * 128 + d], s1 = sinp[s * 128 + d];
    float c2 = cosp[s * 128 + d + 64], s2 = sinp[s * 128 + d + 64];
    float* base = Q + (size_t)s * H_DIM + h * 128;
    float x1 = base[d], x2 = base[d + 64];
    base[d] = x1 * c1 - x2 * s1;
    base[d + 64] = x2 * c2 + x1 * s2;
  } else if (idx < total_q + total_k) {
    idx -= total_q;
    int d = idx & 63;
    int h = (idx >> 6) & 7;
    int s = idx >> 9;
    float c1 = cosp[s * 128 + d], s1 = sinp[s * 128 + d];
    float c2 = cosp[s * 128 + d + 64], s2 = sinp[s * 128 + d + 64];
    float* base = K + (size_t)s * (NKVH * HDIM) + h * 128;
    float x1 = base[d], x2 = base[d + 64];
    base[d] = x1 * c1 - x2 * s1;
    base[d + 64] = x2 * c2 + x1 * s2;
  }
}

// ---------------------------------------------------------------------------
// Causal flash attention, fp32, GQA (unchanged)
// ---------------------------------------------------------------------------
__global__ __launch_bounds__(256) void flash_attn(
    const float* __restrict__ Q, const float* __restrict__ K,
    const float* __restrict__ V, float* __restrict__ Ctx) {
  extern __shared__ float smf[];
  float* Qts = smf;
  float* Kts = smf + 8192;
  float* Vs = smf + 16384;
  float* Ps = smf + 24576;

  const int tid = threadIdx.x;
  const int tx = tid & 15, ty = tid >> 4;
  const int qb = blockIdx.x, hq = blockIdx.y, hkv = hq >> 2;
  const float scale = 0.08838834764831845f;

#pragma unroll
  for (int t = 0; t < 8; ++t) {
    int idx = tid + t * 256;
    int r = idx >> 5;
    int d = (idx & 31) << 2;
    float4 q = *(const float4*)&Q[(size_t)(qb * 64 + r) * H_DIM + hq * 128 + d];
    Qts[(d + 0) * 64 + r] = q.x;
    Qts[(d + 1) * 64 + r] = q.y;
    Qts[(d + 2) * 64 + r] = q.z;
    Qts[(d + 3) * 64 + r] = q.w;
  }

  float o[4][8];
  float m_i[4], l_i[4];
#pragma unroll
  for (int i = 0; i < 4; i++) {
    m_i[i] = -1e30f;
    l_i[i] = 0.f;
#pragma unroll
    for (int j = 0; j < 8; j++) o[i][j] = 0.f;
  }

  for (int kb = 0; kb <= qb; ++kb) {
#pragma unroll
    for (int t = 0; t < 8; ++t) {
      int idx = tid + t * 256;
      int r = idx >> 5;
      int d = (idx & 31) << 2;
      size_t g = (size_t)(kb * 64 + r) * (NKVH * HDIM) + hkv * 128 + d;
      float4 k = *(const float4*)&K[g];
      Kts[(d + 0) * 64 + r] = k.x;
      Kts[(d + 1) * 64 + r] = k.y;
      Kts[(d + 2) * 64 + r] = k.z;
      Kts[(d + 3) * 64 + r] = k.w;
      float4 v = *(const float4*)&V[g];
      *(float4*)&Vs[r * 128 + d] = v;
    }
    __syncthreads();

    float s[4][4];
#pragma unroll
    for (int i = 0; i < 4; i++)
#pragma unroll
      for (int j = 0; j < 4; j++) s[i][j] = 0.f;

#pragma unroll 4
    for (int d = 0; d < 128; ++d) {
      float4 a4 = *(const float4*)&Qts[d * 64 + ty * 4];
      float4 b4 = *(const float4*)&Kts[d * 64 + tx * 4];
      float a[4] = {a4.x, a4.y, a4.z, a4.w};
      float b[4] = {b4.x, b4.y, b4.z, b4.w};
#pragma unroll
      for (int i = 0; i < 4; i++)
#pragma unroll
        for (int j = 0; j < 4; j++) s[i][j] = fmaf(a[i], b[j], s[i][j]);
    }

#pragma unroll
    for (int i = 0; i < 4; i++)
#pragma unroll
      for (int j = 0; j < 4; j++) s[i][j] *= scale;

    if (kb == qb) {
#pragma unroll
      for (int i = 0; i < 4; i++)
#pragma unroll
        for (int j = 0; j < 4; j++)
          if (tx * 4 + j > ty * 4 + i) s[i][j] = -1e30f;
    }

#pragma unroll
    for (int i = 0; i < 4; i++) {
      float mx = fmaxf(fmaxf(s[i][0], s[i][1]), fmaxf(s[i][2], s[i][3]));
      mx = fmaxf(mx, __shfl_xor_sync(0xffffffffu, mx, 1));
      mx = fmaxf(mx, __shfl_xor_sync(0xffffffffu, mx, 2));
      mx = fmaxf(mx, __shfl_xor_sync(0xffffffffu, mx, 4));
      mx = fmaxf(mx, __shfl_xor_sync(0xffffffffu, mx, 8));
      float mnew = fmaxf(m_i[i], mx);
      float al = __expf(m_i[i] - mnew);
      float sum = 0.f;
#pragma unroll
      for (int j = 0; j < 4; j++) {
        s[i][j] = __expf(s[i][j] - mnew);
        sum += s[i][j];
      }
      sum += __shfl_xor_sync(0xffffffffu, sum, 1);
      sum += __shfl_xor_sync(0xffffffffu, sum, 2);
      sum += __shfl_xor_sync(0xffffffffu, sum, 4);
      sum += __shfl_xor_sync(0xffffffffu, sum, 8);
      l_i[i] = l_i[i] * al + sum;
      m_i[i] = mnew;
#pragma unroll
      for (int j = 0; j < 8; j++) o[i][j] *= al;
      *(float4*)&Ps[(ty * 4 + i) * 64 + tx * 4] =
          make_float4(s[i][0], s[i][1], s[i][2], s[i][3]);
    }
    __syncthreads();

#pragma unroll 2
    for (int kk = 0; kk < 64; ++kk) {
      float p0 = Ps[(ty * 4 + 0) * 64 + kk];
      float p1 = Ps[(ty * 4 + 1) * 64 + kk];
      float p2 = Ps[(ty * 4 + 2) * 64 + kk];
      float p3 = Ps[(ty * 4 + 3) * 64 + kk];
      float4 v0 = *(const float4*)&Vs[kk * 128 + tx * 8];
      float4 v1 = *(const float4*)&Vs[kk * 128 + tx * 8 + 4];
      float vv[8] = {v0.x, v0.y, v0.z, v0.w, v1.x, v1.y, v1.z, v1.w};
#pragma unroll
      for (int j = 0; j < 8; j++) {
        o[0][j] = fmaf(p0, vv[j], o[0][j]);
        o[1][j] = fmaf(p1, vv[j], o[1][j]);
        o[2][j] = fmaf(p2, vv[j], o[2][j]);
        o[3][j] = fmaf(p3, vv[j], o[3][j]);
      }
    }
    __syncthreads();
  }

#pragma unroll
  for (int i = 0; i < 4; i++) {
    float inv = 1.0f / l_i[i];
    float* Cp = Ctx + (size_t)(qb * 64 + ty * 4 + i) * H_DIM + hq * 128 + tx * 8;
    *(float4*)Cp =
        make_float4(o[i][0] * inv, o[i][1] * inv, o[i][2] * inv, o[i][3] * inv);
    *(float4*)(Cp + 4) =
        make_float4(o[i][4] * inv, o[i][5] * inv, o[i][6] * inv, o[i][7] * inv);
  }
}

// ---------------------------------------------------------------------------
// Launch
// ---------------------------------------------------------------------------
extern "C" void kernel_launch(void* const* d_in, const int* in_sizes, int n_in,
                              void* d_out, int out_size) {
  const float* X = (const float*)d_in[0];
  const float* cosp = (const float*)d_in[1];
  const float* sinp = (const float*)d_in[2];
  const float* wq = (const float*)d_in[3];
  const float* wk = (const float*)d_in[4];
  const float* wv = (const float*)d_in[5];
  const float* wo = (const float*)d_in[6];
  float* out = (float*)d_out;

  float *Q, *K, *V, *Ctx;
  __nv_bfloat16 *Ahi, *Alo, *Bhi, *Blo;
  cudaGetSymbolAddress((void**)&Q, g_Q);
  cudaGetSymbolAddress((void**)&K, g_K);
  cudaGetSymbolAddress((void**)&V, g_V);
  cudaGetSymbolAddress((void**)&Ctx, g_Ctx);
  cudaGetSymbolAddress((void**)&Ahi, g_Ahi);
  cudaGetSymbolAddress((void**)&Alo, g_Alo);
  cudaGetSymbolAddress((void**)&Bhi, g_Bhi);
  cudaGetSymbolAddress((void**)&Blo, g_Blo);

  const int FLASH_SMEM = 114688;
  cudaFuncSetAttribute(flash_attn, cudaFuncAttributeMaxDynamicSharedMemorySize,
                       FLASH_SMEM);
  cudaFuncSetAttribute(gemm_mma, cudaFuncAttributeMaxDynamicSharedMemorySize,
                       GEMM_SMEM);

  dim3 blk(256);
  dim3 tblk(32, 8);

  // Activations -> bf16 split
  split_convert<<<(S_LEN * KDIM / 4 + 255) / 256, 256>>>(X, Ahi, Alo,
                                                         S_LEN * KDIM);
  // Q projection
  transpose_split<<<dim3(4096 / 32, KDIM / 32), tblk>>>(wq, Bhi, Blo, KDIM, 4096);
  gemm_mma<<<dim3(32, 16), blk, GEMM_SMEM>>>(Ahi, Alo, Bhi, Blo, Q, 4096);
  // K projection
  transpose_split<<<dim3(1024 / 32, KDIM / 32), tblk>>>(wk, Bhi, Blo, KDIM, 1024);
  gemm_mma<<<dim3(8, 16), blk, GEMM_SMEM>>>(Ahi, Alo, Bhi, Blo, K, 1024);
  // V projection
  transpose_split<<<dim3(1024 / 32, KDIM / 32), tblk>>>(wv, Bhi, Blo, KDIM, 1024);
  gemm_mma<<<dim3(8, 16), blk, GEMM_SMEM>>>(Ahi, Alo, Bhi, Blo, V, 1024);
  // RoPE
  int rope_total = S_LEN * (NQH + NKVH) * 64;
  rope_kernel<<<(rope_total + 255) / 256, 256>>>(Q, K, cosp, sinp);
  // Attention
  flash_attn<<<dim3(32, 32), blk, FLASH_SMEM>>>(Q, K, V, Ctx);
  // Output projection (reuse activation split buffers for Ctx)
  split_convert<<<(S_LEN * KDIM / 4 + 255) / 256, 256>>>(Ctx, Ahi, Alo,
                                                         S_LEN * KDIM);
  transpose_split<<<dim3(4096 / 32, KDIM / 32), tblk>>>(wo, Bhi, Blo, KDIM, 4096);
  gemm_mma<<<dim3(32, 16), blk, GEMM_SMEM>>>(Ahi, Alo, Bhi, Blo, out, 4096);
}

// round 7
// speedup vs baseline: 2.7437x; 1.6900x over previous
#include <cuda_runtime.h>
#include <cuda_bf16.h>
#include <math.h>
#include <stdint.h>

#define S_LEN 2048
#define H_DIM 4096
#define NQH 32
#define NKVH 8
#define HDIM 128
#define KDIM 4096
#define NQKV 6144

// ---------------------------------------------------------------------------
// Scratch (device globals; no allocation allowed)
// ---------------------------------------------------------------------------
__device__ float g_QKV[S_LEN * NQKV];          // fused QKV projection output
__device__ float g_Ctx[S_LEN * H_DIM];

__device__ __nv_bfloat16 g_Ahi[S_LEN * KDIM];  // activations hi
__device__ __nv_bfloat16 g_Alo[S_LEN * KDIM];  // activations lo
__device__ __nv_bfloat16 g_Bhi[NQKV * KDIM];   // weights (transposed [N,K]) hi
__device__ __nv_bfloat16 g_Blo[NQKV * KDIM];   // weights lo

// attention operands (bf16 split, rope+scale applied)
__device__ __nv_bfloat16 g_Qh[S_LEN * NQH * HDIM];
__device__ __nv_bfloat16 g_Ql[S_LEN * NQH * HDIM];
__device__ __nv_bfloat16 g_Kh[S_LEN * NKVH * HDIM];
__device__ __nv_bfloat16 g_Kl[S_LEN * NKVH * HDIM];
__device__ __nv_bfloat16 g_Vh[S_LEN * NKVH * HDIM];
__device__ __nv_bfloat16 g_Vl[S_LEN * NKVH * HDIM];

// ---------------------------------------------------------------------------
// Helpers
// ---------------------------------------------------------------------------
__device__ __forceinline__ uint32_t smem_u32(const void* p) {
  uint32_t a;
  asm("{ .reg .u64 t; cvta.to.shared.u64 t, %1; cvt.u32.u64 %0, t; }"
      : "=r"(a) : "l"(p));
  return a;
}

__device__ __forceinline__ void cp16(uint32_t dst, const void* src) {
  asm volatile("cp.async.cg.shared.global [%0], [%1], 16;" ::"r"(dst), "l"(src));
}

#define LDSM4(R, ADDR)                                                         \
  asm volatile("ldmatrix.sync.aligned.m8n8.x4.shared.b16 {%0,%1,%2,%3}, [%4];" \
               : "=r"((R)[0]), "=r"((R)[1]), "=r"((R)[2]), "=r"((R)[3])        \
               : "r"(ADDR))

#define LDSM4T(R, ADDR)                                                        \
  asm volatile(                                                                \
      "ldmatrix.sync.aligned.m8n8.x4.trans.shared.b16 {%0,%1,%2,%3}, [%4];"    \
      : "=r"((R)[0]), "=r"((R)[1]), "=r"((R)[2]), "=r"((R)[3])                 \
      : "r"(ADDR))

#define MMA16816(D, A, B)                                                      \
  asm volatile(                                                                \
      "mma.sync.aligned.m16n8k16.row.col.f32.bf16.bf16.f32 "                   \
      "{%0,%1,%2,%3}, {%4,%5,%6,%7}, {%8,%9}, {%0,%1,%2,%3};"                  \
      : "+f"((D)[0]), "+f"((D)[1]), "+f"((D)[2]), "+f"((D)[3])                 \
      : "r"((A)[0]), "r"((A)[1]), "r"((A)[2]), "r"((A)[3]), "r"((B)[0]),       \
        "r"((B)[1]))

__device__ __forceinline__ uint32_t bf2bits(__nv_bfloat162 v) {
  return *reinterpret_cast<uint32_t*>(&v);
}

// ---------------------------------------------------------------------------
// Split-convert fp32 -> bf16 hi/lo (row-major, same layout)
// ---------------------------------------------------------------------------
__global__ void split_convert(const float* __restrict__ X,
                              __nv_bfloat16* __restrict__ Hi,
                              __nv_bfloat16* __restrict__ Lo, int n) {
  int i = (blockIdx.x * 256 + threadIdx.x) * 4;
  if (i >= n) return;
  float4 x = *(const float4*)(X + i);
  float v[4] = {x.x, x.y, x.z, x.w};
  __nv_bfloat16 h[4], l[4];
#pragma unroll
  for (int j = 0; j < 4; j++) {
    h[j] = __float2bfloat16_rn(v[j]);
    l[j] = __float2bfloat16_rn(v[j] - __bfloat162float(h[j]));
  }
  __nv_bfloat162 h01, h23, l01, l23;
  h01.x = h[0]; h01.y = h[1]; h23.x = h[2]; h23.y = h[3];
  l01.x = l[0]; l01.y = l[1]; l23.x = l[2]; l23.y = l[3];
  *(__nv_bfloat162*)(Hi + i) = h01;
  *(__nv_bfloat162*)(Hi + i + 2) = h23;
  *(__nv_bfloat162*)(Lo + i) = l01;
  *(__nv_bfloat162*)(Lo + i + 2) = l23;
}

// ---------------------------------------------------------------------------
// Transpose-convert W[K,N] fp32 -> [N,K] bf16 hi/lo
// ---------------------------------------------------------------------------
__global__ void transpose_split(const float* __restrict__ W,
                                __nv_bfloat16* __restrict__ Hi,
                                __nv_bfloat16* __restrict__ Lo, int K, int N) {
  __shared__ float tile[32][33];
  int tx = threadIdx.x, ty = threadIdx.y;
  int k0 = blockIdx.y * 32, n0 = blockIdx.x * 32;
#pragma unroll
  for (int i = 0; i < 4; i++)
    tile[ty + i * 8][tx] = W[(size_t)(k0 + ty + i * 8) * N + n0 + tx];
  __syncthreads();
#pragma unroll
  for (int i = 0; i < 4; i++) {
    float v = tile[tx][ty + i * 8];
    __nv_bfloat16 h = __float2bfloat16_rn(v);
    __nv_bfloat16 l = __float2bfloat16_rn(v - __bfloat162float(h));
    size_t o = (size_t)(n0 + ty + i * 8) * K + k0 + tx;
    Hi[o] = h;
    Lo[o] = l;
  }
}

// ---------------------------------------------------------------------------
// HMMA bf16 split-precision GEMM (unchanged from passing round)
// ---------------------------------------------------------------------------
#define NCH (KDIM / 32)
#define MAT_BYTES 10240       // 128 * 40 * 2
#define STAGE_BYTES 40960
#define GEMM_SMEM (3 * STAGE_BYTES)  // 122880

__global__ __launch_bounds__(256, 1) void gemm_mma(
    const __nv_bfloat16* __restrict__ Ahi, const __nv_bfloat16* __restrict__ Alo,
    const __nv_bfloat16* __restrict__ Bhi, const __nv_bfloat16* __restrict__ Blo,
    float* __restrict__ C, int N) {
  extern __shared__ char smc[];
  const int tid = threadIdx.x;
  const int lane = tid & 31, wid = tid >> 5;
  const int wm = wid & 1, wn = wid >> 1;
  const int bm = blockIdx.y * 128, bn = blockIdx.x * 128;
  const size_t Kb = (size_t)KDIM * 2;

  uint32_t sbase = smem_u32(smc);

  const char* gp0 = (const char*)Ahi + (size_t)bm * Kb;
  const char* gp1 = (const char*)Alo + (size_t)bm * Kb;
  const char* gp2 = (const char*)Bhi + (size_t)bn * Kb;
  const char* gp3 = (const char*)Blo + (size_t)bn * Kb;

  const int r = tid >> 2;
  const int cb = (tid & 3) * 16;

  auto load_stage = [&](int stage, int k0) {
    uint32_t sb = sbase + stage * STAGE_BYTES;
    size_t gk = (size_t)k0 * 2;
    const char* gp[4] = {gp0, gp1, gp2, gp3};
#pragma unroll
    for (int m = 0; m < 4; m++) {
      uint32_t sd = sb + m * MAT_BYTES;
#pragma unroll
      for (int j = 0; j < 2; j++) {
        int rr = r + j * 64;
        cp16(sd + rr * 80 + cb, gp[m] + (size_t)rr * Kb + gk + cb);
      }
    }
    asm volatile("cp.async.commit_group;" ::: "memory");
  };

  float acc[4][4][4];
#pragma unroll
  for (int a = 0; a < 4; a++)
#pragma unroll
    for (int b = 0; b < 4; b++)
#pragma unroll
      for (int c = 0; c < 4; c++) acc[a][b][c] = 0.f;

  const int arow = wm * 64 + (lane & 15);
  const int aoff = (lane >> 4) * 8;
  const int brow = wn * 32 + (lane >> 4) * 8 + (lane & 7);
  const int boff = ((lane >> 3) & 1) * 8;

  load_stage(0, 0);
  load_stage(1, 32);

  for (int i = 0; i < NCH; ++i) {
    if (i + 2 < NCH)
      asm volatile("cp.async.wait_group 1;" ::: "memory");
    else
      asm volatile("cp.async.wait_group 0;" ::: "memory");
    __syncthreads();
    if (i + 2 < NCH) load_stage((i + 2) % 3, (i + 2) * 32);

    uint32_t sb = sbase + (i % 3) * STAGE_BYTES;
    uint32_t sAh = sb;
    uint32_t sBh = sb + 2 * MAT_BYTES;

#pragma unroll
    for (int ks = 0; ks < 32; ks += 16) {
      uint32_t Ah[4][4], Al[4][4], Bh[4][2], Bl[4][2];
#pragma unroll
      for (int mi = 0; mi < 4; mi++) {
        uint32_t ad = sAh + ((arow + mi * 16) * 40 + ks + aoff) * 2;
        LDSM4(Ah[mi], ad);
        LDSM4(Al[mi], ad + MAT_BYTES);
      }
#pragma unroll
      for (int ni = 0; ni < 2; ni++) {
        uint32_t bd = sBh + ((brow + ni * 16) * 40 + ks + boff) * 2;
        uint32_t t[4];
        LDSM4(t, bd);
        Bh[ni * 2][0] = t[0]; Bh[ni * 2][1] = t[1];
        Bh[ni * 2 + 1][0] = t[2]; Bh[ni * 2 + 1][1] = t[3];
        LDSM4(t, bd + MAT_BYTES);
        Bl[ni * 2][0] = t[0]; Bl[ni * 2][1] = t[1];
        Bl[ni * 2 + 1][0] = t[2]; Bl[ni * 2 + 1][1] = t[3];
      }
#pragma unroll
      for (int mi = 0; mi < 4; mi++)
#pragma unroll
        for (int nj = 0; nj < 4; nj++) {
          MMA16816(acc[mi][nj], Ah[mi], Bh[nj]);
          MMA16816(acc[mi][nj], Ah[mi], Bl[nj]);
          MMA16816(acc[mi][nj], Al[mi], Bh[nj]);
        }
    }
  }

  const int tg = lane >> 2, tc = (lane & 3) * 2;
#pragma unroll
  for (int mi = 0; mi < 4; mi++) {
    int row = bm + wm * 64 + mi * 16 + tg;
#pragma unroll
    for (int nj = 0; nj < 4; nj++) {
      int col = bn + wn * 32 + nj * 8 + tc;
      float* p = C + (size_t)row * N + col;
      p[0] = acc[mi][nj][0];
      p[1] = acc[mi][nj][1];
      float* p2 = p + 8 * (size_t)N;
      p2[0] = acc[mi][nj][2];
      p2[1] = acc[mi][nj][3];
    }
  }
}

// ---------------------------------------------------------------------------
// RoPE + scale + bf16 split. Q gets rope+softmax scale, K gets rope, V plain.
// QKV fused layout: [s][6144] with Q at 0, K at 4096, V at 5120.
// ---------------------------------------------------------------------------
#define FA_SCALE 0.08838834764831845f

__global__ void rope_split(const float* __restrict__ QKV,
                           const float* __restrict__ cosp,
                           const float* __restrict__ sinp) {
  int idx = blockIdx.x * blockDim.x + threadIdx.x;
  const int nq = S_LEN * NQH * 64;      // 4194304
  const int nk = S_LEN * NKVH * 64;     // 1048576
  if (idx < nq) {
    int d = idx & 63;
    int h = (idx >> 6) & 31;
    int s = idx >> 11;
    const float* src = QKV + (size_t)s * NQKV + h * 128;
    float c1 = cosp[s * 128 + d], s1 = sinp[s * 128 + d];
    float c2 = cosp[s * 128 + d + 64], s2 = sinp[s * 128 + d + 64];
    float x1 = src[d], x2 = src[d + 64];
    float y1 = (x1 * c1 - x2 * s1) * FA_SCALE;
    float y2 = (x2 * c2 + x1 * s2) * FA_SCALE;
    size_t o = ((size_t)s * NQH + h) * 128 + d;
    __nv_bfloat16 h1 = __float2bfloat16_rn(y1);
    __nv_bfloat16 h2 = __float2bfloat16_rn(y2);
    g_Qh[o] = h1;
    g_Ql[o] = __float2bfloat16_rn(y1 - __bfloat162float(h1));
    g_Qh[o + 64] = h2;
    g_Ql[o + 64] = __float2bfloat16_rn(y2 - __bfloat162float(h2));
  } else if (idx < nq + nk) {
    int t = idx - nq;
    int d = t & 63;
    int h = (t >> 6) & 7;
    int s = t >> 9;
    const float* src = QKV + (size_t)s * NQKV + 4096 + h * 128;
    float c1 = cosp[s * 128 + d], s1 = sinp[s * 128 + d];
    float c2 = cosp[s * 128 + d + 64], s2 = sinp[s * 128 + d + 64];
    float x1 = src[d], x2 = src[d + 64];
    float y1 = x1 * c1 - x2 * s1;
    float y2 = x2 * c2 + x1 * s2;
    size_t o = ((size_t)s * NKVH + h) * 128 + d;
    __nv_bfloat16 h1 = __float2bfloat16_rn(y1);
    __nv_bfloat16 h2 = __float2bfloat16_rn(y2);
    g_Kh[o] = h1;
    g_Kl[o] = __float2bfloat16_rn(y1 - __bfloat162float(h1));
    g_Kh[o + 64] = h2;
    g_Kl[o + 64] = __float2bfloat16_rn(y2 - __bfloat162float(h2));
  } else if (idx < nq + 2 * nk) {
    int t = idx - nq - nk;
    int d = t & 63;
    int h = (t >> 6) & 7;
    int s = t >> 9;
    const float* src = QKV + (size_t)s * NQKV + 5120 + h * 128;
    float x1 = src[d], x2 = src[d + 64];
    size_t o = ((size_t)s * NKVH + h) * 128 + d;
    __nv_bfloat16 h1 = __float2bfloat16_rn(x1);
    __nv_bfloat16 h2 = __float2bfloat16_rn(x2);
    g_Vh[o] = h1;
    g_Vl[o] = __float2bfloat16_rn(x1 - __bfloat162float(h1));
    g_Vh[o + 64] = h2;
    g_Vl[o + 64] = __float2bfloat16_rn(x2 - __bfloat162float(h2));
  }
}

// ---------------------------------------------------------------------------
// HMMA flash attention, causal, GQA. Tile 64(M)x64(N), HD=128.
// 128 threads = 4 warps; warp w owns q-rows w*16..w*16+15.
// Split precision on both matmuls (3 HMMA terms each), fp32 accum.
// SMEM: 6 bf16 matrices 64x128, row stride 136 elems (pad 8) = 104448 B.
// ---------------------------------------------------------------------------
#define FA_STRIDE 136
#define FA_MAT 17408          // 64 * 136 * 2
#define FA_SMEM (6 * FA_MAT)  // 104448

__global__ __launch_bounds__(128) void flash_mma(
    const __nv_bfloat16* __restrict__ Qh_, const __nv_bfloat16* __restrict__ Ql_,
    const __nv_bfloat16* __restrict__ Kh_, const __nv_bfloat16* __restrict__ Kl_,
    const __nv_bfloat16* __restrict__ Vh_, const __nv_bfloat16* __restrict__ Vl_,
    float* __restrict__ Ctx) {
  extern __shared__ char smf[];
  const uint32_t sb = smem_u32(smf);
  const uint32_t sQh = sb;
  const uint32_t sKh = sb + 2 * FA_MAT;
  const uint32_t sVh = sb + 4 * FA_MAT;

  const int tid = threadIdx.x;
  const int lane = tid & 31, w = tid >> 5;
  const int qb = (int)gridDim.x - 1 - (int)blockIdx.x;  // long diagonals first
  const int hq = blockIdx.y, hkv = hq >> 2;

  // Load Q tile (hi+lo) once
#pragma unroll
  for (int j = 0; j < 8; j++) {
    int idx = tid + j * 128;
    int r = idx >> 4;
    int c = (idx & 15) * 16;  // byte offset in 256B row
    size_t g = ((size_t)(qb * 64 + r) * NQH + hq) * 256 + c;
    uint32_t d = r * (FA_STRIDE * 2) + c;
    cp16(sQh + d, (const char*)Qh_ + g);
    cp16(sQh + FA_MAT + d, (const char*)Ql_ + g);
  }
  asm volatile("cp.async.commit_group;" ::: "memory");

  float o[16][4];
#pragma unroll
  for (int t = 0; t < 16; t++)
#pragma unroll
    for (int c = 0; c < 4; c++) o[t][c] = 0.f;
  float m0 = -1e30f, m1 = -1e30f, l0 = 0.f, l1 = 0.f;

  const int arow = w * 16 + (lane & 15);
  const int aoff = (lane >> 4) * 8;
  const int bRow = (lane >> 4) * 8 + (lane & 7);
  const int bCol = ((lane >> 3) & 1) * 8;
  const int vRow = (lane & 7) + ((lane >> 3) & 1) * 8;
  const int vCol = (lane >> 4) * 8;
  const int rloc = w * 16 + (lane >> 2);  // local row of c0/c1 (c2/c3: +8)

  for (int kb = 0; kb <= qb; ++kb) {
    // Load K,V tiles (hi+lo)
#pragma unroll
    for (int j = 0; j < 8; j++) {
      int idx = tid + j * 128;
      int r = idx >> 4;
      int c = (idx & 15) * 16;
      size_t g = ((size_t)(kb * 64 + r) * NKVH + hkv) * 256 + c;
      uint32_t d = r * (FA_STRIDE * 2) + c;
      cp16(sKh + d, (const char*)Kh_ + g);
      cp16(sKh + FA_MAT + d, (const char*)Kl_ + g);
      cp16(sVh + d, (const char*)Vh_ + g);
      cp16(sVh + FA_MAT + d, (const char*)Vl_ + g);
    }
    asm volatile("cp.async.commit_group;" ::: "memory");
    asm volatile("cp.async.wait_group 0;" ::: "memory");
    __syncthreads();

    // S = Q @ K^T  (8 n-tiles of fp32 accum per warp)
    float sacc[8][4];
#pragma unroll
    for (int t = 0; t < 8; t++)
#pragma unroll
      for (int c = 0; c < 4; c++) sacc[t][c] = 0.f;

#pragma unroll
    for (int kk = 0; kk < 8; ++kk) {
      uint32_t qh[4], ql[4];
      uint32_t qa = sQh + (arow * FA_STRIDE + kk * 16 + aoff) * 2;
      LDSM4(qh, qa);
      LDSM4(ql, qa + FA_MAT);
#pragma unroll
      for (int np = 0; np < 4; np++) {
        uint32_t ka = sKh + ((np * 16 + bRow) * FA_STRIDE + kk * 16 + bCol) * 2;
        uint32_t kh[4], kl[4];
        LDSM4(kh, ka);
        LDSM4(kl, ka + FA_MAT);
        MMA16816(sacc[2 * np], qh, kh);
        MMA16816(sacc[2 * np], qh, kl);
        MMA16816(sacc[2 * np], ql, kh);
        MMA16816(sacc[2 * np + 1], qh, kh + 2);
        MMA16816(sacc[2 * np + 1], qh, kl + 2);
        MMA16816(sacc[2 * np + 1], ql, kh + 2);
      }
    }

    // Causal mask on diagonal block
    if (kb == qb) {
#pragma unroll
      for (int t = 0; t < 8; t++) {
        int n = t * 8 + (lane & 3) * 2;
        if (n > rloc) sacc[t][0] = -1e30f;
        if (n + 1 > rloc) sacc[t][1] = -1e30f;
        if (n > rloc + 8) sacc[t][2] = -1e30f;
        if (n + 1 > rloc + 8) sacc[t][3] = -1e30f;
      }
    }

    // Online softmax (rows rloc, rloc+8; stats shared across quad lanes)
    float mx0 = -1e30f, mx1 = -1e30f;
#pragma unroll
    for (int t = 0; t < 8; t++) {
      mx0 = fmaxf(mx0, fmaxf(sacc[t][0], sacc[t][1]));
      mx1 = fmaxf(mx1, fmaxf(sacc[t][2], sacc[t][3]));
    }
    mx0 = fmaxf(mx0, __shfl_xor_sync(0xffffffffu, mx0, 1));
    mx0 = fmaxf(mx0, __shfl_xor_sync(0xffffffffu, mx0, 2));
    mx1 = fmaxf(mx1, __shfl_xor_sync(0xffffffffu, mx1, 1));
    mx1 = fmaxf(mx1, __shfl_xor_sync(0xffffffffu, mx1, 2));
    float mn0 = fmaxf(m0, mx0), mn1 = fmaxf(m1, mx1);
    float al0 = __expf(m0 - mn0), al1 = __expf(m1 - mn1);
    m0 = mn0;
    m1 = mn1;
    float sum0 = 0.f, sum1 = 0.f;
#pragma unroll
    for (int t = 0; t < 8; t++) {
      sacc[t][0] = __expf(sacc[t][0] - m0);
      sacc[t][1] = __expf(sacc[t][1] - m0);
      sacc[t][2] = __expf(sacc[t][2] - m1);
      sacc[t][3] = __expf(sacc[t][3] - m1);
      sum0 += sacc[t][0] + sacc[t][1];
      sum1 += sacc[t][2] + sacc[t][3];
    }
    sum0 += __shfl_xor_sync(0xffffffffu, sum0, 1);
    sum0 += __shfl_xor_sync(0xffffffffu, sum0, 2);
    sum1 += __shfl_xor_sync(0xffffffffu, sum1, 1);
    sum1 += __shfl_xor_sync(0xffffffffu, sum1, 2);
    l0 = l0 * al0 + sum0;
    l1 = l1 * al1 + sum1;
#pragma unroll
    for (int t = 0; t < 16; t++) {
      o[t][0] *= al0;
      o[t][1] *= al0;
      o[t][2] *= al1;
      o[t][3] *= al1;
    }

    // O += P @ V  (split P and V)
#pragma unroll
    for (int j = 0; j < 4; j++) {
      uint32_t pha[4], pla[4];
      {
        __nv_bfloat162 h01 = __floats2bfloat162_rn(sacc[2 * j][0], sacc[2 * j][1]);
        __nv_bfloat162 h23 = __floats2bfloat162_rn(sacc[2 * j][2], sacc[2 * j][3]);
        pha[0] = bf2bits(h01);
        pha[1] = bf2bits(h23);
        pla[0] = bf2bits(__floats2bfloat162_rn(
            sacc[2 * j][0] - __low2float(h01), sacc[2 * j][1] - __high2float(h01)));
        pla[1] = bf2bits(__floats2bfloat162_rn(
            sacc[2 * j][2] - __low2float(h23), sacc[2 * j][3] - __high2float(h23)));
        __nv_bfloat162 g01 =
            __floats2bfloat162_rn(sacc[2 * j + 1][0], sacc[2 * j + 1][1]);
        __nv_bfloat162 g23 =
            __floats2bfloat162_rn(sacc[2 * j + 1][2], sacc[2 * j + 1][3]);
        pha[2] = bf2bits(g01);
        pha[3] = bf2bits(g23);
        pla[2] = bf2bits(__floats2bfloat162_rn(sacc[2 * j + 1][0] - __low2float(g01),
                                               sacc[2 * j + 1][1] - __high2float(g01)));
        pla[3] = bf2bits(__floats2bfloat162_rn(sacc[2 * j + 1][2] - __low2float(g23),
                                               sacc[2 * j + 1][3] - __high2float(g23)));
      }
#pragma unroll
      for (int np = 0; np < 8; np++) {
        uint32_t va = sVh + ((j * 16 + vRow) * FA_STRIDE + np * 16 + vCol) * 2;
        uint32_t vh[4], vl[4];
        LDSM4T(vh, va);
        LDSM4T(vl, va + FA_MAT);
        MMA16816(o[2 * np], pha, vh);
        MMA16816(o[2 * np], pha, vl);
        MMA16816(o[2 * np], pla, vh);
        MMA16816(o[2 * np + 1], pha, vh + 2);
        MMA16816(o[2 * np + 1], pha, vl + 2);
        MMA16816(o[2 * np + 1], pla, vh + 2);
      }
    }
    __syncthreads();  // protect K/V smem before next block's loads
  }

  // Epilogue
  float inv0 = 1.0f / l0, inv1 = 1.0f / l1;
  int r0 = qb * 64 + rloc;
#pragma unroll
  for (int t = 0; t < 16; t++) {
    int col = t * 8 + (lane & 3) * 2;
    float* p0 = Ctx + ((size_t)r0 * NQH + hq) * 128 + col;
    *(float2*)p0 = make_float2(o[t][0] * inv0, o[t][1] * inv0);
    float* p1 = Ctx + ((size_t)(r0 + 8) * NQH + hq) * 128 + col;
    *(float2*)p1 = make_float2(o[t][2] * inv1, o[t][3] * inv1);
  }
}

// ---------------------------------------------------------------------------
// Launch
// ---------------------------------------------------------------------------
extern "C" void kernel_launch(void* const* d_in, const int* in_sizes, int n_in,
                              void* d_out, int out_size) {
  const float* X = (const float*)d_in[0];
  const float* cosp = (const float*)d_in[1];
  const float* sinp = (const float*)d_in[2];
  const float* wq = (const float*)d_in[3];
  const float* wk = (const float*)d_in[4];
  const float* wv = (const float*)d_in[5];
  const float* wo = (const float*)d_in[6];
  float* out = (float*)d_out;

  float *QKV, *Ctx;
  __nv_bfloat16 *Ahi, *Alo, *Bhi, *Blo, *Qh, *Ql, *Kh, *Kl, *Vh, *Vl;
  cudaGetSymbolAddress((void**)&QKV, g_QKV);
  cudaGetSymbolAddress((void**)&Ctx, g_Ctx);
  cudaGetSymbolAddress((void**)&Ahi, g_Ahi);
  cudaGetSymbolAddress((void**)&Alo, g_Alo);
  cudaGetSymbolAddress((void**)&Bhi, g_Bhi);
  cudaGetSymbolAddress((void**)&Blo, g_Blo);
  cudaGetSymbolAddress((void**)&Qh, g_Qh);
  cudaGetSymbolAddress((void**)&Ql, g_Ql);
  cudaGetSymbolAddress((void**)&Kh, g_Kh);
  cudaGetSymbolAddress((void**)&Kl, g_Kl);
  cudaGetSymbolAddress((void**)&Vh, g_Vh);
  cudaGetSymbolAddress((void**)&Vl, g_Vl);

  cudaFuncSetAttribute(gemm_mma, cudaFuncAttributeMaxDynamicSharedMemorySize,
                       GEMM_SMEM);
  cudaFuncSetAttribute(flash_mma, cudaFuncAttributeMaxDynamicSharedMemorySize,
                       FA_SMEM);

  dim3 blk(256);
  dim3 tblk(32, 8);

  // Activations -> bf16 split
  split_convert<<<(S_LEN * KDIM / 4 + 255) / 256, 256>>>(X, Ahi, Alo,
                                                         S_LEN * KDIM);
  // Fused QKV weights -> [N,K] bf16 split (rows: q 0..4095, k 4096.., v 5120..)
  transpose_split<<<dim3(128, 128), tblk>>>(wq, Bhi, Blo, KDIM, 4096);
  transpose_split<<<dim3(32, 128), tblk>>>(wk, Bhi + (size_t)4096 * KDIM,
                                           Blo + (size_t)4096 * KDIM, KDIM, 1024);
  transpose_split<<<dim3(32, 128), tblk>>>(wv, Bhi + (size_t)5120 * KDIM,
                                           Blo + (size_t)5120 * KDIM, KDIM, 1024);
  // Fused QKV projection
  gemm_mma<<<dim3(48, 16), blk, GEMM_SMEM>>>(Ahi, Alo, Bhi, Blo, QKV, NQKV);
  // RoPE + scale + split for attention
  int rtot = S_LEN * NQH * 64 + 2 * S_LEN * NKVH * 64;
  rope_split<<<(rtot + 255) / 256, 256>>>(QKV, cosp, sinp);
  // Attention (HMMA)
  flash_mma<<<dim3(32, 32), dim3(128), FA_SMEM>>>(Qh, Ql, Kh, Kl, Vh, Vl, Ctx);
  // Output projection
  split_convert<<<(S_LEN * KDIM / 4 + 255) / 256, 256>>>(Ctx, Ahi, Alo,
                                                         S_LEN * KDIM);
  transpose_split<<<dim3(128, 128), tblk>>>(wo, Bhi, Blo, KDIM, 4096);
  gemm_mma<<<dim3(32, 16), blk, GEMM_SMEM>>>(Ahi, Alo, Bhi, Blo, out, 4096);
}